// round 13
// baseline (speedup 1.0000x reference)
#include <cuda_runtime.h>
#include <cuda_fp16.h>
#include <math.h>
#include <stdint.h>

// ---------------- problem constants ----------------
#define B_  64
#define N_  256
#define D_  512
#define E_  10
#define M_  (B_*N_)        // 16384
#define KX_ (E_*D_)        // 5120  (edge part of stage-B K)
#define KB_ (KX_+D_)       // 5632  (edge-hi + self-hi)
#define KI_B64 (KB_/64)    // 88 k64-iters (stage B)
#define KSLF64 (KX_/64)    // 80 = k64-iter where self segment starts

typedef __half fp16;

// ---------------- device scratch (static; no runtime allocation) ----------
__device__ unsigned g_bits[(size_t)E_*B_*N_*8];      // graphs bitmask, packed-j rank space
__device__ float    g_invneigh[M_];
__device__ float    g_w[M_];
__device__ float    g_nodeA[(size_t)M_*D_];          // fp32 node ping buffer
__device__ fp16     g_Bstack[(size_t)D_*KB_];        // [d][kk]: Wedge_hi | Wself_hi
__device__ fp16     g_Zt[(size_t)B_*D_*N_];          // [b][d][jr] packed ranks, zero-pad
__device__ fp16     g_Xhi[(size_t)M_*KX_];           // packed-rank rows
__device__ fp16     g_nhi[(size_t)M_*D_], g_nhi2[(size_t)M_*D_];
// mask packing
__device__ int      g_gperm[M_];     // rank -> orig row (actives first, global)
__device__ int      g_cnt[B_];       // active count per batch
__device__ int      g_aoff[B_+1];    // prefix of g_cnt
__device__ int      g_acnt;          // total active rows

// ---------------- PTX helpers ----------------------------------------------
__device__ __forceinline__ uint32_t smem_u32(const void* p){
    uint32_t a; asm("{ .reg .u64 t; cvta.to.shared.u64 t, %1; cvt.u32.u64 %0, t; }"
                    : "=r"(a) : "l"(p)); return a;
}
__device__ __forceinline__ void cpa16(uint32_t dst, const void* src){
    asm volatile("cp.async.cg.shared.global [%0], [%1], 16;" :: "r"(dst), "l"(src));
}
#define CP_COMMIT() asm volatile("cp.async.commit_group;" ::: "memory")
#define CP_WAIT1()  asm volatile("cp.async.wait_group 1;" ::: "memory")
#define CP_WAIT2()  asm volatile("cp.async.wait_group 2;" ::: "memory")

__device__ __forceinline__ void ldsm_x4(uint32_t* r, uint32_t addr){
    asm volatile("ldmatrix.sync.aligned.m8n8.x4.shared.b16 {%0,%1,%2,%3}, [%4];"
        : "=r"(r[0]),"=r"(r[1]),"=r"(r[2]),"=r"(r[3]) : "r"(addr));
}
__device__ __forceinline__ void mma16816(float* c, const uint32_t* a, const uint32_t* b){
    asm volatile("mma.sync.aligned.m16n8k16.row.col.f32.f16.f16.f32 "
        "{%0,%1,%2,%3},{%4,%5,%6,%7},{%8,%9},{%0,%1,%2,%3};"
        : "+f"(c[0]),"+f"(c[1]),"+f"(c[2]),"+f"(c[3])
        : "r"(a[0]),"r"(a[1]),"r"(a[2]),"r"(a[3]), "r"(b[0]),"r"(b[1]));
}

// gemmB smem: 3 stages, As[128][72]+Bs[128][72] (BK=64, 128x128 tile, 2 CTAs/SM)
#define OFFB_B 18432
#define STG_B  36864
#define SMEM_B_DYN (3*STG_B)          // 110592
// gemmA smem: 4 stages, As[64][40]+Bs[256][40]
#define STG_A  25600
#define OFFB_A 5120
#define SMEM_A_DYN (4*STG_A)          // 102400

// warp tile MT*16 x NP*32; KH k16-chunks; PITCH = smem row pitch (elements)
template<int MT, int NP, int KH, int PITCH>
__device__ __forceinline__ void warp_compute_t(uint32_t sA, uint32_t sB,
                                               int m_off, int n_off,
                                               float c[][2*NP][4], int lane){
    #pragma unroll
    for (int kh = 0; kh < KH; ++kh){
        int k16 = kh*16;
        uint32_t a[MT][4];
        #pragma unroll
        for (int mt = 0; mt < MT; ++mt){
            int row = m_off + mt*16 + (lane & 15);
            ldsm_x4(a[mt], sA + (uint32_t)(row*PITCH + k16 + ((lane>>4)<<3))*2);
        }
        uint32_t bfr[NP][4];
        #pragma unroll
        for (int np = 0; np < NP; ++np){
            int row = n_off + np*16 + (lane & 7) + ((lane>>4)&1)*8;
            ldsm_x4(bfr[np], sB + (uint32_t)(row*PITCH + k16 + (((lane>>3)&1)<<3))*2);
        }
        #pragma unroll
        for (int mt = 0; mt < MT; ++mt)
            #pragma unroll
            for (int nt = 0; nt < 2*NP; ++nt)
                mma16816(c[mt][nt], a[mt], &bfr[nt>>1][(nt&1)*2]);
    }
}

// ---------------- preprocessing kernels ------------------------------------
__global__ void k_perm(const int* __restrict__ mask){
    __shared__ int sc[B_+1];
    int wid = threadIdx.x >> 5, lane = threadIdx.x & 31;
    for (int b = wid; b < B_; b += 32){
        int cnt = 0;
        #pragma unroll
        for (int c = 0; c < 8; ++c){
            unsigned bal = __ballot_sync(0xffffffffu, mask[b*N_ + c*32 + lane] != 0);
            cnt += __popc(bal);
        }
        if (lane == 0){ sc[b] = cnt; g_cnt[b] = cnt; }
    }
    __syncthreads();
    if (threadIdx.x == 0){
        int a = 0;
        for (int b = 0; b < B_; ++b){ g_aoff[b] = a; int t = sc[b]; sc[b] = a; a += t; }
        g_aoff[B_] = a; g_acnt = a; sc[B_] = a;
    }
    __syncthreads();
    for (int b = wid; b < B_; b += 32){
        int apos = sc[b];
        int mpos = sc[B_] + (b*N_ - sc[b]);
        #pragma unroll
        for (int c = 0; c < 8; ++c){
            int orig = b*N_ + c*32 + lane;
            int bit = mask[orig] != 0;
            unsigned bal = __ballot_sync(0xffffffffu, bit);
            unsigned ltm = (1u << lane) - 1u;
            if (bit) g_gperm[apos + __popc(bal & ltm)] = orig;
            else     g_gperm[mpos + __popc(~bal & ltm)] = orig;
            apos += __popc(bal);
            mpos += 32 - __popc(bal);
        }
    }
}
// bitmask in packed-j rank space; two-phase for coalesced adj reads
__global__ void k_bits(const int* __restrict__ adj, const int* __restrict__ mask){
    __shared__ unsigned char flags[8][N_];
    int warp = threadIdx.x >> 5, lane = threadIdx.x & 31;
    int r = blockIdx.x * 8 + warp;          // (e*B+b)*N + i
    int b = (r / N_) % B_;
    int i = r % N_;
    int mi = mask[b*N_ + i];
    const int* arow = adj + (size_t)r * N_;
    #pragma unroll
    for (int c = 0; c < 8; ++c){
        int j = c*32 + lane;
        flags[warp][j] = (unsigned char)(mi && arow[j] && mask[b*N_ + j] && (j != i));
    }
    __syncwarp();
    int cnt = g_cnt[b], aoff = g_aoff[b];
    unsigned keep = 0;
    #pragma unroll
    for (int c = 0; c < 8; c++){
        int jr = c*32 + lane;
        int bit = 0;
        if (jr < cnt){
            int jloc = g_gperm[aoff + jr] - b*N_;
            bit = flags[warp][jloc];
        }
        unsigned wrd = __ballot_sync(0xffffffffu, bit != 0);
        if (lane == c) keep = wrd;
    }
    if (lane < 8) g_bits[(size_t)r*8 + lane] = keep;
}
__global__ void k_neigh(){
    int t = blockIdx.x*blockDim.x + threadIdx.x;
    int b = t / N_;
    int s = 0;
    for (int e = 0; e < E_; e++){
        const unsigned* row = g_bits + (size_t)((e*B_+b)*N_ + (t % N_))*8;
        #pragma unroll
        for (int c = 0; c < 8; c++) s += __popc(row[c]);
    }
    float n = (float)s; if (n < 1.f) n = 1.f;
    g_invneigh[t] = 1.f / n;
}
__global__ void k_bstack(const float* __restrict__ We, const float* __restrict__ Ws){
    int idx = blockIdx.x*256 + threadIdx.x;
    if (idx >= D_*KB_) return;
    int d = idx / KB_, kk = idx % KB_;
    float w;
    if (kk < KX_){
        int e = kk / D_, k2 = kk % D_;
        w = We[((size_t)e*D_ + d)*D_ + k2];
    } else {
        w = Ws[(size_t)d*D_ + (kk - KX_)];
    }
    g_Bstack[(size_t)d*KB_ + kk] = __float2half(w);
}
__global__ void k_zeroX(){
    int r = g_acnt + blockIdx.y;
    if (r >= M_ || r >= ((g_acnt + 127) & ~127)) return;
    int c = blockIdx.x*256 + threadIdx.x;
    ((uint32_t*)(g_Xhi + (size_t)r*KX_))[c] = 0u;
}

// ---------------- per-iteration elementwise kernels -------------------------
__global__ void k_w(const float* __restrict__ node0, int useScratch,
                    const float* __restrict__ Wnw, const float* __restrict__ bnw,
                    float* __restrict__ woutBase, int it){
    int warp = threadIdx.x >> 5, lane = threadIdx.x & 31;
    int r = blockIdx.x*8 + warp;
    const float* node = useScratch ? g_nodeA : node0;
    const float4* nr = (const float4*)(node + (size_t)r*D_);
    const float4* wr = (const float4*)Wnw;
    float s = 0.f;
    #pragma unroll
    for (int c = 0; c < 4; c++){
        float4 a = nr[c*32 + lane], w = wr[c*32 + lane];
        s += a.x*w.x + a.y*w.y + a.z*w.z + a.w*w.w;
        if (!useScratch){
            fp16 h0=__float2half(a.x), h1=__float2half(a.y);
            fp16 h2=__float2half(a.z), h3=__float2half(a.w);
            uint2 pk;
            pk.x = (uint32_t)__half_as_ushort(h0) | ((uint32_t)__half_as_ushort(h1) << 16);
            pk.y = (uint32_t)__half_as_ushort(h2) | ((uint32_t)__half_as_ushort(h3) << 16);
            *(uint2*)(g_nhi + (size_t)r*D_ + (c*32 + lane)*4) = pk;
        }
    }
    #pragma unroll
    for (int o = 16; o; o >>= 1) s += __shfl_down_sync(0xffffffffu, s, o);
    if (lane == 0){
        float z = s + bnw[0];
        float w = 1.f / (1.f + expf(-z));
        g_w[r] = w;
        int b = r / N_, n = r % N_;
        woutBase[(size_t)b*(2*N_) + it*N_ + n] = w;
    }
}
__global__ void k_zt(const float* __restrict__ node0, int useScratch){
    __shared__ float s[32][33];
    const float* node = useScratch ? g_nodeA : node0;
    int b = blockIdx.z, d0 = blockIdx.x*32, j0 = blockIdx.y*32;
    int tx = threadIdx.x, ty = threadIdx.y;
    int jr = j0 + ty;
    int cnt = g_cnt[b], aoff = g_aoff[b];
    float v = 0.f;
    if (jr < cnt){
        int orig = g_gperm[aoff + jr];
        v = node[(size_t)orig*D_ + d0 + tx] * g_w[orig];
    }
    s[ty][tx] = v;
    __syncthreads();
    g_Zt[((size_t)b*D_ + d0 + ty)*N_ + j0 + tx] = __float2half(s[tx][ty]);
}

// ---------------- stage A GEMM: Xhi[rank] = fp16((G@Zt)*inv_neigh) ----------
// CTA tile 64x256 (m-tile 64), K packed to ceil(cnt/32)*32  (round-9/11 design)
__global__ void __launch_bounds__(256, 1) k_gemmA(){
    extern __shared__ char dsm[];
    uint32_t sbase = smem_u32(dsm);
    int tid = threadIdx.x, wid = tid >> 5, lane = tid & 31;
    int dBase = blockIdx.x * 256;           // 0 or 256
    int y = blockIdx.y;                     // be*4 + mq
    int mq = y & 3; int be = y >> 2;
    int e = be % E_, b = be / E_;
    int cnt = g_cnt[b];
    int mBase = mq * 64;
    if (mBase >= cnt) return;
    int aoff = g_aoff[b];
    int m_off = (wid >> 2) * 32;
    int n_off = (wid & 3) * 64;
    int KI = (cnt + 31) >> 5;

    const fp16* Zbase = g_Zt + ((size_t)b*D_ + dBase) * (size_t)N_;
    const unsigned* bitbase = g_bits + (size_t)((size_t)e*B_ + b)*N_*8;

    int rA = tid >> 2, qsel = tid & 3;      // A expand: row 0..63, 8-bit quarter
    int rankA = mBase + rA;
    bool av = rankA < cnt;
    int iloc = av ? (g_gperm[aoff + rankA] - b*N_) : 0;

    auto loadB = [&](int itk, int s){
        uint32_t sB = sbase + s*STG_A + OFFB_A;
        const fp16* src = Zbase + (size_t)tid*N_ + itk*32;
        uint32_t d0 = sB + (uint32_t)(tid*40)*2;
        cpa16(d0,      src);
        cpa16(d0 + 16, src + 8);
        cpa16(d0 + 32, src + 16);
        cpa16(d0 + 48, src + 24);
        CP_COMMIT();
    };
    auto expandA = [&](int itk, int s){
        unsigned w32 = av ? bitbase[(size_t)iloc*8 + itk] : 0u;
        unsigned bits8 = (w32 >> (qsel*8)) & 0xFFu;
        uint32_t u[4];
        #pragma unroll
        for (int q = 0; q < 4; ++q){
            u[q] = ((bits8 >> (2*q)) & 1u ? 0x3C00u : 0u)
                 | ((bits8 >> (2*q+1)) & 1u ? 0x3C000000u : 0u);
        }
        *(uint4*)(dsm + s*STG_A + (rA*40 + qsel*8)*2) = make_uint4(u[0],u[1],u[2],u[3]);
    };

    float c[2][8][4];
    #pragma unroll
    for (int i = 0; i < 2; ++i)
        #pragma unroll
        for (int j = 0; j < 8; ++j)
            #pragma unroll
            for (int q = 0; q < 4; ++q) c[i][j][q] = 0.f;

    expandA(0, 0);
    loadB(0, 0); loadB(1, 1); loadB(2, 2);   // beyond-KI loads hit zero-padded Zt
    for (int it = 0; it < KI; ++it){
        CP_WAIT2();
        __syncthreads();
        if (it + 1 < KI) expandA(it + 1, (it + 1) & 3);
        if (it + 3 < KI) loadB(it + 3, (it + 3) & 3); else CP_COMMIT();
        int s = it & 3;
        warp_compute_t<2,4,2,40>(sbase + s*STG_A, sbase + s*STG_A + OFFB_A,
                                 m_off, n_off, c, lane);
    }

    #pragma unroll
    for (int mt = 0; mt < 2; ++mt){
        int rk1 = mBase + m_off + mt*16 + (lane >> 2);
        int rk2 = rk1 + 8;
        bool v1 = rk1 < cnt, v2 = rk2 < cnt;
        float inv1 = 0.f, inv2 = 0.f;
        int gr1 = aoff + rk1, gr2 = aoff + rk2;
        if (v1) inv1 = g_invneigh[g_gperm[gr1]];
        if (v2) inv2 = g_invneigh[g_gperm[gr2]];
        #pragma unroll
        for (int nt = 0; nt < 8; ++nt){
            int col = e*D_ + dBase + n_off + nt*8 + (lane & 3)*2;
            if (v1){
                fp16 h0 = __float2half(c[mt][nt][0]*inv1);
                fp16 h1 = __float2half(c[mt][nt][1]*inv1);
                *(uint32_t*)(g_Xhi + (size_t)gr1*KX_ + col) =
                    (uint32_t)__half_as_ushort(h0) | ((uint32_t)__half_as_ushort(h1) << 16);
            }
            if (v2){
                fp16 h2 = __float2half(c[mt][nt][2]*inv2);
                fp16 h3 = __float2half(c[mt][nt][3]*inv2);
                *(uint32_t*)(g_Xhi + (size_t)gr2*KX_ + col) =
                    (uint32_t)__half_as_ushort(h2) | ((uint32_t)__half_as_ushort(h3) << 16);
            }
        }
    }
}

// ---------------- stage B GEMM (rank space): out = relu([X|n]@W + b) --------
// CTA tile 128x128, BK=64, 3 stages, 2 CTAs/SM
__global__ void __launch_bounds__(256, 2) k_gemmB(const float* __restrict__ bself,
                                                  float* __restrict__ out0,
                                                  int srcSel, int outMode){
    extern __shared__ char dsm[];
    uint32_t sbase = smem_u32(dsm);
    int tid = threadIdx.x, wid = tid >> 5, lane = tid & 31;
    int dBase = blockIdx.x * 128;           // 0..3
    int mBase = blockIdx.y * 128;
    int m_off = (wid >> 2) * 64;            // 2 m-groups
    int n_off = (wid & 3) * 32;             // 4 n-groups of 32
    int acnt = g_acnt;
    int kStart = (mBase >= acnt) ? KSLF64 : 0;

    const fp16* NHI = srcSel ? g_nhi2 : g_nhi;
    int rA = tid >> 1, cA = (tid & 1)*32;   // row 0..127, element col 0 or 32
    int morig = g_gperm[mBase + rA];

    auto load = [&](int itk, int s){
        uint32_t sA = sbase + s*STG_B;
        uint32_t sB = sA + OFFB_B;
        int rr = itk * 64;
        const fp16* Arow;
        if (rr < KX_) Arow = g_Xhi + (size_t)(mBase + rA)*KX_ + rr;
        else          Arow = NHI + (size_t)morig*D_ + (rr - KX_);
        uint32_t dA = sA + (uint32_t)(rA*72 + cA)*2;
        cpa16(dA,      Arow + cA);
        cpa16(dA + 16, Arow + cA + 8);
        cpa16(dA + 32, Arow + cA + 16);
        cpa16(dA + 48, Arow + cA + 24);
        const fp16* Brow = g_Bstack + (size_t)(dBase + rA)*KB_ + rr;
        uint32_t dB = sB + (uint32_t)(rA*72 + cA)*2;
        cpa16(dB,      Brow + cA);
        cpa16(dB + 16, Brow + cA + 8);
        cpa16(dB + 32, Brow + cA + 16);
        cpa16(dB + 48, Brow + cA + 24);
        CP_COMMIT();
    };

    float c[4][4][4];
    #pragma unroll
    for (int i = 0; i < 4; ++i)
        #pragma unroll
        for (int j = 0; j < 4; ++j)
            #pragma unroll
            for (int q = 0; q < 4; ++q) c[i][j][q] = 0.f;

    load(kStart, 0); load(kStart+1, 1);
    for (int it = kStart; it < KI_B64; ++it){
        CP_WAIT1();
        __syncthreads();
        if (it + 2 < KI_B64) load(it + 2, (it + 2 - kStart) % 3); else CP_COMMIT();
        int s = (it - kStart) % 3;
        warp_compute_t<4,2,4,72>(sbase + s*STG_B, sbase + s*STG_B + OFFB_B,
                                 m_off, n_off, c, lane);
    }

    #pragma unroll
    for (int mt = 0; mt < 4; ++mt){
        int m1 = mBase + m_off + mt*16 + (lane >> 2);
        int o1 = g_gperm[m1], o2 = g_gperm[m1 + 8];
        #pragma unroll
        for (int nt = 0; nt < 4; ++nt){
            int n = dBase + n_off + nt*8 + (lane & 3)*2;
            float bi0 = __ldg(bself + n), bi1 = __ldg(bself + n + 1);
            float v0 = c[mt][nt][0] + bi0, v1 = c[mt][nt][1] + bi1;
            float v2 = c[mt][nt][2] + bi0, v3 = c[mt][nt][3] + bi1;
            v0 = v0 > 0.f ? v0 : 0.f; v1 = v1 > 0.f ? v1 : 0.f;
            v2 = v2 > 0.f ? v2 : 0.f; v3 = v3 > 0.f ? v3 : 0.f;
            if (outMode){
                *(float2*)(g_nodeA + (size_t)o1*D_ + n) = make_float2(v0, v1);
                *(float2*)(g_nodeA + (size_t)o2*D_ + n) = make_float2(v2, v3);
                fp16 h0=__float2half(v0), h1=__float2half(v1);
                fp16 h2=__float2half(v2), h3=__float2half(v3);
                *(uint32_t*)(g_nhi2 + (size_t)o1*D_ + n) = (uint32_t)__half_as_ushort(h0)|((uint32_t)__half_as_ushort(h1)<<16);
                *(uint32_t*)(g_nhi2 + (size_t)o2*D_ + n) = (uint32_t)__half_as_ushort(h2)|((uint32_t)__half_as_ushort(h3)<<16);
            } else {
                *(float2*)(out0 + (size_t)o1*D_ + n) = make_float2(v0, v1);
                *(float2*)(out0 + (size_t)o2*D_ + n) = make_float2(v2, v3);
            }
        }
    }
}

// ---------------- launch ----------------------------------------------------
extern "C" void kernel_launch(void* const* d_in, const int* in_sizes, int n_in,
                              void* d_out, int out_size){
    const float* node  = (const float*)d_in[0];
    const float* Wnw   = (const float*)d_in[1];
    const float* bnw   = (const float*)d_in[2];
    const float* Wself = (const float*)d_in[3];
    const float* bself = (const float*)d_in[4];
    const float* Wedge = (const float*)d_in[5];
    const int*   mask  = (const int*)d_in[6];
    const int*   adj   = (const int*)d_in[7];

    float* out  = (float*)d_out;
    float* outW = out + (size_t)M_*D_;

    cudaFuncSetAttribute(k_gemmA, cudaFuncAttributeMaxDynamicSharedMemorySize, SMEM_A_DYN);
    cudaFuncSetAttribute(k_gemmB, cudaFuncAttributeMaxDynamicSharedMemorySize, SMEM_B_DYN);

    // iteration-invariant preprocessing
    k_bstack<<<(D_*KB_ + 255)/256, 256>>>(Wedge, Wself);
    k_perm  <<<1, 1024>>>(mask);
    k_bits  <<<(E_*B_*N_)/8, 256>>>(adj, mask);
    k_neigh <<<M_/256, 256>>>();
    k_zeroX <<<dim3(10, 128), 256>>>();

    // ---- iteration 0: node -> g_nodeA (+ nhi2) ----
    k_w    <<<M_/8, 256>>>(node, 0, Wnw, bnw, outW, 0);
    k_zt   <<<dim3(16, 8, B_), dim3(32, 32)>>>(node, 0);
    k_gemmA<<<dim3(2, B_*E_*4), 256, SMEM_A_DYN>>>();
    k_gemmB<<<dim3(4, M_/128), 256, SMEM_B_DYN>>>(bself, out, 0, 1);

    // ---- iteration 1: g_nodeA -> d_out ----
    k_w    <<<M_/8, 256>>>(node, 1, Wnw, bnw, outW, 1);
    k_zt   <<<dim3(16, 8, B_), dim3(32, 32)>>>(node, 1);
    k_gemmA<<<dim3(2, B_*E_*4), 256, SMEM_A_DYN>>>();
    k_gemmB<<<dim3(4, M_/128), 256, SMEM_B_DYN>>>(bself, out, 1, 0);
}

// round 14
// speedup vs baseline: 1.1753x; 1.1753x over previous
#include <cuda_runtime.h>
#include <cuda_fp16.h>
#include <math.h>
#include <stdint.h>

// ---------------- problem constants ----------------
#define B_  64
#define N_  256
#define D_  512
#define E_  10
#define M_  (B_*N_)        // 16384
#define KX_ (E_*D_)        // 5120  (edge part of stage-B K)
#define KB_ (KX_+D_)       // 5632  (edge-hi + self-hi)
#define KI_B (KB_/32)      // 176 k-iters (stage B)
#define KSLF (KX_/32)      // 160 = k-iter where self segment starts

typedef __half fp16;

// ---------------- device scratch (static; no runtime allocation) ----------
__device__ unsigned g_bits[(size_t)E_*B_*N_*8];      // graphs bitmask, packed-j rank space
__device__ float    g_invneigh[M_];
__device__ float    g_w[M_];
__device__ float    g_nodeA[(size_t)M_*D_];          // fp32 node ping buffer
__device__ fp16     g_Bstack[(size_t)D_*KB_];        // [d][kk]: Wedge_hi | Wself_hi
__device__ fp16     g_Zt[(size_t)B_*D_*N_];          // [b][d][jr] packed ranks, zero-pad
__device__ fp16     g_Xhi[(size_t)M_*KX_];           // packed-rank rows
__device__ fp16     g_nhi[(size_t)M_*D_], g_nhi2[(size_t)M_*D_];
// mask packing
__device__ int      g_gperm[M_];     // rank -> orig row (actives first, global)
__device__ int      g_cnt[B_];       // active count per batch
__device__ int      g_aoff[B_+1];    // prefix of g_cnt
__device__ int      g_acnt;          // total active rows

// ---------------- PTX helpers ----------------------------------------------
__device__ __forceinline__ uint32_t smem_u32(const void* p){
    uint32_t a; asm("{ .reg .u64 t; cvta.to.shared.u64 t, %1; cvt.u32.u64 %0, t; }"
                    : "=r"(a) : "l"(p)); return a;
}
__device__ __forceinline__ void cpa16(uint32_t dst, const void* src){
    asm volatile("cp.async.cg.shared.global [%0], [%1], 16;" :: "r"(dst), "l"(src));
}
#define CP_COMMIT() asm volatile("cp.async.commit_group;" ::: "memory")
#define CP_WAIT2()  asm volatile("cp.async.wait_group 2;" ::: "memory")

__device__ __forceinline__ void ldsm_x4(uint32_t* r, uint32_t addr){
    asm volatile("ldmatrix.sync.aligned.m8n8.x4.shared.b16 {%0,%1,%2,%3}, [%4];"
        : "=r"(r[0]),"=r"(r[1]),"=r"(r[2]),"=r"(r[3]) : "r"(addr));
}
__device__ __forceinline__ void mma16816(float* c, const uint32_t* a, const uint32_t* b){
    asm volatile("mma.sync.aligned.m16n8k16.row.col.f32.f16.f16.f32 "
        "{%0,%1,%2,%3},{%4,%5,%6,%7},{%8,%9},{%0,%1,%2,%3};"
        : "+f"(c[0]),"+f"(c[1]),"+f"(c[2]),"+f"(c[3])
        : "r"(a[0]),"r"(a[1]),"r"(a[2]),"r"(a[3]), "r"(b[0]),"r"(b[1]));
}

// gemmB smem: 4 stages, As[128][40]+Bs[128][40] (128x128 tile, 2 CTAs/SM)
#define STG_B  20480
#define OFFB_B 10240
#define SMEM_B_DYN (4*STG_B)          // 81920
// gemmA smem: 4 stages, As[64][40]+Bs[256][40], 2 CTAs/SM
#define STG_A  25600
#define OFFB_A 5120
#define SMEM_A_DYN (4*STG_A)          // 102400

// warp tile MT*16 x NP*32 (MT m-frags, 2*NP n-frags of 8)
template<int MT, int NP>
__device__ __forceinline__ void warp_compute_t(uint32_t sA, uint32_t sB,
                                               int m_off, int n_off,
                                               float c[][2*NP][4], int lane){
    #pragma unroll
    for (int kh = 0; kh < 2; ++kh){
        int k16 = kh*16;
        uint32_t a[MT][4];
        #pragma unroll
        for (int mt = 0; mt < MT; ++mt){
            int row = m_off + mt*16 + (lane & 15);
            ldsm_x4(a[mt], sA + (uint32_t)(row*40 + k16 + ((lane>>4)<<3))*2);
        }
        uint32_t bfr[NP][4];
        #pragma unroll
        for (int np = 0; np < NP; ++np){
            int row = n_off + np*16 + (lane & 7) + ((lane>>4)&1)*8;
            ldsm_x4(bfr[np], sB + (uint32_t)(row*40 + k16 + (((lane>>3)&1)<<3))*2);
        }
        #pragma unroll
        for (int mt = 0; mt < MT; ++mt)
            #pragma unroll
            for (int nt = 0; nt < 2*NP; ++nt)
                mma16816(c[mt][nt], a[mt], &bfr[nt>>1][(nt&1)*2]);
    }
}

// ---------------- preprocessing kernels ------------------------------------
__global__ void k_perm(const int* __restrict__ mask){
    __shared__ int sc[B_+1];
    int wid = threadIdx.x >> 5, lane = threadIdx.x & 31;
    for (int b = wid; b < B_; b += 32){
        int cnt = 0;
        #pragma unroll
        for (int c = 0; c < 8; ++c){
            unsigned bal = __ballot_sync(0xffffffffu, mask[b*N_ + c*32 + lane] != 0);
            cnt += __popc(bal);
        }
        if (lane == 0){ sc[b] = cnt; g_cnt[b] = cnt; }
    }
    __syncthreads();
    if (threadIdx.x == 0){
        int a = 0;
        for (int b = 0; b < B_; ++b){ g_aoff[b] = a; int t = sc[b]; sc[b] = a; a += t; }
        g_aoff[B_] = a; g_acnt = a; sc[B_] = a;
    }
    __syncthreads();
    for (int b = wid; b < B_; b += 32){
        int apos = sc[b];
        int mpos = sc[B_] + (b*N_ - sc[b]);
        #pragma unroll
        for (int c = 0; c < 8; ++c){
            int orig = b*N_ + c*32 + lane;
            int bit = mask[orig] != 0;
            unsigned bal = __ballot_sync(0xffffffffu, bit);
            unsigned ltm = (1u << lane) - 1u;
            if (bit) g_gperm[apos + __popc(bal & ltm)] = orig;
            else     g_gperm[mpos + __popc(~bal & ltm)] = orig;
            apos += __popc(bal);
            mpos += 32 - __popc(bal);
        }
    }
}
// bitmask in packed-j rank space; two-phase for coalesced adj reads
__global__ void k_bits(const int* __restrict__ adj, const int* __restrict__ mask){
    __shared__ unsigned char flags[8][N_];
    int warp = threadIdx.x >> 5, lane = threadIdx.x & 31;
    int r = blockIdx.x * 8 + warp;          // (e*B+b)*N + i
    int b = (r / N_) % B_;
    int i = r % N_;
    int mi = mask[b*N_ + i];
    const int* arow = adj + (size_t)r * N_;
    #pragma unroll
    for (int c = 0; c < 8; ++c){
        int j = c*32 + lane;
        flags[warp][j] = (unsigned char)(mi && arow[j] && mask[b*N_ + j] && (j != i));
    }
    __syncwarp();
    int cnt = g_cnt[b], aoff = g_aoff[b];
    unsigned keep = 0;
    #pragma unroll
    for (int c = 0; c < 8; c++){
        int jr = c*32 + lane;
        int bit = 0;
        if (jr < cnt){
            int jloc = g_gperm[aoff + jr] - b*N_;
            bit = flags[warp][jloc];
        }
        unsigned wrd = __ballot_sync(0xffffffffu, bit != 0);
        if (lane == c) keep = wrd;
    }
    if (lane < 8) g_bits[(size_t)r*8 + lane] = keep;
}
__global__ void k_neigh(){
    int t = blockIdx.x*blockDim.x + threadIdx.x;
    int b = t / N_;
    int s = 0;
    for (int e = 0; e < E_; e++){
        const unsigned* row = g_bits + (size_t)((e*B_+b)*N_ + (t % N_))*8;
        #pragma unroll
        for (int c = 0; c < 8; c++) s += __popc(row[c]);
    }
    float n = (float)s; if (n < 1.f) n = 1.f;
    g_invneigh[t] = 1.f / n;
}
__global__ void k_bstack(const float* __restrict__ We, const float* __restrict__ Ws){
    int idx = blockIdx.x*256 + threadIdx.x;
    if (idx >= D_*KB_) return;
    int d = idx / KB_, kk = idx % KB_;
    float w;
    if (kk < KX_){
        int e = kk / D_, k2 = kk % D_;
        w = We[((size_t)e*D_ + d)*D_ + k2];
    } else {
        w = Ws[(size_t)d*D_ + (kk - KX_)];
    }
    g_Bstack[(size_t)d*KB_ + kk] = __float2half(w);
}
__global__ void k_zeroX(){
    int r = g_acnt + blockIdx.y;
    if (r >= M_ || r >= ((g_acnt + 127) & ~127)) return;
    int c = blockIdx.x*256 + threadIdx.x;
    ((uint32_t*)(g_Xhi + (size_t)r*KX_))[c] = 0u;
}

// ---------------- per-iteration elementwise kernels -------------------------
__global__ void k_w(const float* __restrict__ node0, int useScratch,
                    const float* __restrict__ Wnw, const float* __restrict__ bnw,
                    float* __restrict__ woutBase, int it){
    int warp = threadIdx.x >> 5, lane = threadIdx.x & 31;
    int r = blockIdx.x*8 + warp;
    const float* node = useScratch ? g_nodeA : node0;
    const float4* nr = (const float4*)(node + (size_t)r*D_);
    const float4* wr = (const float4*)Wnw;
    float s = 0.f;
    #pragma unroll
    for (int c = 0; c < 4; c++){
        float4 a = nr[c*32 + lane], w = wr[c*32 + lane];
        s += a.x*w.x + a.y*w.y + a.z*w.z + a.w*w.w;
        if (!useScratch){
            fp16 h0=__float2half(a.x), h1=__float2half(a.y);
            fp16 h2=__float2half(a.z), h3=__float2half(a.w);
            uint2 pk;
            pk.x = (uint32_t)__half_as_ushort(h0) | ((uint32_t)__half_as_ushort(h1) << 16);
            pk.y = (uint32_t)__half_as_ushort(h2) | ((uint32_t)__half_as_ushort(h3) << 16);
            *(uint2*)(g_nhi + (size_t)r*D_ + (c*32 + lane)*4) = pk;
        }
    }
    #pragma unroll
    for (int o = 16; o; o >>= 1) s += __shfl_down_sync(0xffffffffu, s, o);
    if (lane == 0){
        float z = s + bnw[0];
        float w = 1.f / (1.f + expf(-z));
        g_w[r] = w;
        int b = r / N_, n = r % N_;
        woutBase[(size_t)b*(2*N_) + it*N_ + n] = w;
    }
}
__global__ void k_zt(const float* __restrict__ node0, int useScratch){
    __shared__ float s[32][33];
    const float* node = useScratch ? g_nodeA : node0;
    int b = blockIdx.z, d0 = blockIdx.x*32, j0 = blockIdx.y*32;
    int tx = threadIdx.x, ty = threadIdx.y;
    int jr = j0 + ty;
    int cnt = g_cnt[b], aoff = g_aoff[b];
    float v = 0.f;
    if (jr < cnt){
        int orig = g_gperm[aoff + jr];
        v = node[(size_t)orig*D_ + d0 + tx] * g_w[orig];
    }
    s[ty][tx] = v;
    __syncthreads();
    g_Zt[((size_t)b*D_ + d0 + ty)*N_ + j0 + tx] = __float2half(s[tx][ty]);
}

// ---------------- stage A GEMM: Xhi[rank] = fp16((G@Zt)*inv_neigh) ----------
// CTA tile 64x256 (m-tile 64), K packed to ceil(cnt/32)*32  (round-9/11 design,
// now 2 CTAs/SM)
__global__ void __launch_bounds__(256, 2) k_gemmA(){
    extern __shared__ char dsm[];
    uint32_t sbase = smem_u32(dsm);
    int tid = threadIdx.x, wid = tid >> 5, lane = tid & 31;
    int dBase = blockIdx.x * 256;           // 0 or 256
    int y = blockIdx.y;                     // be*4 + mq
    int mq = y & 3; int be = y >> 2;
    int e = be % E_, b = be / E_;
    int cnt = g_cnt[b];
    int mBase = mq * 64;
    if (mBase >= cnt) return;
    int aoff = g_aoff[b];
    int m_off = (wid >> 2) * 32;
    int n_off = (wid & 3) * 64;
    int KI = (cnt + 31) >> 5;

    const fp16* Zbase = g_Zt + ((size_t)b*D_ + dBase) * (size_t)N_;
    const unsigned* bitbase = g_bits + (size_t)((size_t)e*B_ + b)*N_*8;

    int rA = tid >> 2, qsel = tid & 3;      // A expand: row 0..63, 8-bit quarter
    int rankA = mBase + rA;
    bool av = rankA < cnt;
    int iloc = av ? (g_gperm[aoff + rankA] - b*N_) : 0;

    auto loadB = [&](int itk, int s){
        uint32_t sB = sbase + s*STG_A + OFFB_A;
        const fp16* src = Zbase + (size_t)tid*N_ + itk*32;
        uint32_t d0 = sB + (uint32_t)(tid*40)*2;
        cpa16(d0,      src);
        cpa16(d0 + 16, src + 8);
        cpa16(d0 + 32, src + 16);
        cpa16(d0 + 48, src + 24);
        CP_COMMIT();
    };
    auto expandA = [&](int itk, int s){
        unsigned w32 = av ? bitbase[(size_t)iloc*8 + itk] : 0u;
        unsigned bits8 = (w32 >> (qsel*8)) & 0xFFu;
        uint32_t u[4];
        #pragma unroll
        for (int q = 0; q < 4; ++q){
            u[q] = ((bits8 >> (2*q)) & 1u ? 0x3C00u : 0u)
                 | ((bits8 >> (2*q+1)) & 1u ? 0x3C000000u : 0u);
        }
        *(uint4*)(dsm + s*STG_A + (rA*40 + qsel*8)*2) = make_uint4(u[0],u[1],u[2],u[3]);
    };

    float c[2][8][4];
    #pragma unroll
    for (int i = 0; i < 2; ++i)
        #pragma unroll
        for (int j = 0; j < 8; ++j)
            #pragma unroll
            for (int q = 0; q < 4; ++q) c[i][j][q] = 0.f;

    expandA(0, 0);
    loadB(0, 0); loadB(1, 1); loadB(2, 2);   // beyond-KI loads hit zero-padded Zt
    for (int it = 0; it < KI; ++it){
        CP_WAIT2();
        __syncthreads();
        if (it + 1 < KI) expandA(it + 1, (it + 1) & 3);
        if (it + 3 < KI) loadB(it + 3, (it + 3) & 3); else CP_COMMIT();
        int s = it & 3;
        warp_compute_t<2,4>(sbase + s*STG_A, sbase + s*STG_A + OFFB_A,
                            m_off, n_off, c, lane);
    }

    #pragma unroll
    for (int mt = 0; mt < 2; ++mt){
        int rk1 = mBase + m_off + mt*16 + (lane >> 2);
        int rk2 = rk1 + 8;
        bool v1 = rk1 < cnt, v2 = rk2 < cnt;
        float inv1 = 0.f, inv2 = 0.f;
        int gr1 = aoff + rk1, gr2 = aoff + rk2;
        if (v1) inv1 = g_invneigh[g_gperm[gr1]];
        if (v2) inv2 = g_invneigh[g_gperm[gr2]];
        #pragma unroll
        for (int nt = 0; nt < 8; ++nt){
            int col = e*D_ + dBase + n_off + nt*8 + (lane & 3)*2;
            if (v1){
                fp16 h0 = __float2half(c[mt][nt][0]*inv1);
                fp16 h1 = __float2half(c[mt][nt][1]*inv1);
                *(uint32_t*)(g_Xhi + (size_t)gr1*KX_ + col) =
                    (uint32_t)__half_as_ushort(h0) | ((uint32_t)__half_as_ushort(h1) << 16);
            }
            if (v2){
                fp16 h2 = __float2half(c[mt][nt][2]*inv2);
                fp16 h3 = __float2half(c[mt][nt][3]*inv2);
                *(uint32_t*)(g_Xhi + (size_t)gr2*KX_ + col) =
                    (uint32_t)__half_as_ushort(h2) | ((uint32_t)__half_as_ushort(h3) << 16);
            }
        }
    }
}

// ---------------- stage B GEMM (rank space): out = relu([X|n]@W + b) --------
// CTA tile 128x128, BK=32, 4 stages, 2 CTAs/SM (round-11 verified optimum)
__global__ void __launch_bounds__(256, 2) k_gemmB(const float* __restrict__ bself,
                                                  float* __restrict__ out0,
                                                  int srcSel, int outMode){
    extern __shared__ char dsm[];
    uint32_t sbase = smem_u32(dsm);
    int tid = threadIdx.x, wid = tid >> 5, lane = tid & 31;
    int dBase = blockIdx.x * 128;           // 0..3
    int mBase = blockIdx.y * 128;
    int m_off = (wid >> 2) * 64;            // 2 m-groups
    int n_off = (wid & 3) * 32;             // 4 n-groups of 32
    int acnt = g_acnt;
    int kStart = (mBase >= acnt) ? KSLF : 0;

    const fp16* NHI = srcSel ? g_nhi2 : g_nhi;
    int rA = tid >> 1, cA = (tid & 1)*2;
    int morig = g_gperm[mBase + rA];

    auto load = [&](int itk, int s){
        uint32_t sA = sbase + s*STG_B;
        uint32_t sB = sA + OFFB_B;
        int rr = itk * 32;
        const fp16* Arow;
        if (rr < KX_) Arow = g_Xhi + (size_t)(mBase + rA)*KX_ + rr;
        else          Arow = NHI + (size_t)morig*D_ + (rr - KX_);
        uint32_t dA = sA + (uint32_t)(rA*40 + cA*8)*2;
        cpa16(dA,      Arow + cA*8);
        cpa16(dA + 16, Arow + cA*8 + 8);
        const fp16* Brow = g_Bstack + (size_t)(dBase + rA)*KB_ + rr;
        uint32_t dB = sB + (uint32_t)(rA*40 + cA*8)*2;
        cpa16(dB,      Brow + cA*8);
        cpa16(dB + 16, Brow + cA*8 + 8);
        CP_COMMIT();
    };

    float c[4][4][4];
    #pragma unroll
    for (int i = 0; i < 4; ++i)
        #pragma unroll
        for (int j = 0; j < 4; ++j)
            #pragma unroll
            for (int q = 0; q < 4; ++q) c[i][j][q] = 0.f;

    load(kStart, 0); load(kStart+1, 1); load(kStart+2, 2);
    for (int it = kStart; it < KI_B; ++it){
        CP_WAIT2();
        __syncthreads();
        if (it + 3 < KI_B) load(it + 3, (it + 3 - kStart) & 3); else CP_COMMIT();
        int s = (it - kStart) & 3;
        warp_compute_t<4,2>(sbase + s*STG_B, sbase + s*STG_B + OFFB_B,
                            m_off, n_off, c, lane);
    }

    #pragma unroll
    for (int mt = 0; mt < 4; ++mt){
        int m1 = mBase + m_off + mt*16 + (lane >> 2);
        int o1 = g_gperm[m1], o2 = g_gperm[m1 + 8];
        #pragma unroll
        for (int nt = 0; nt < 4; ++nt){
            int n = dBase + n_off + nt*8 + (lane & 3)*2;
            float bi0 = __ldg(bself + n), bi1 = __ldg(bself + n + 1);
            float v0 = c[mt][nt][0] + bi0, v1 = c[mt][nt][1] + bi1;
            float v2 = c[mt][nt][2] + bi0, v3 = c[mt][nt][3] + bi1;
            v0 = v0 > 0.f ? v0 : 0.f; v1 = v1 > 0.f ? v1 : 0.f;
            v2 = v2 > 0.f ? v2 : 0.f; v3 = v3 > 0.f ? v3 : 0.f;
            if (outMode){
                *(float2*)(g_nodeA + (size_t)o1*D_ + n) = make_float2(v0, v1);
                *(float2*)(g_nodeA + (size_t)o2*D_ + n) = make_float2(v2, v3);
                fp16 h0=__float2half(v0), h1=__float2half(v1);
                fp16 h2=__float2half(v2), h3=__float2half(v3);
                *(uint32_t*)(g_nhi2 + (size_t)o1*D_ + n) = (uint32_t)__half_as_ushort(h0)|((uint32_t)__half_as_ushort(h1)<<16);
                *(uint32_t*)(g_nhi2 + (size_t)o2*D_ + n) = (uint32_t)__half_as_ushort(h2)|((uint32_t)__half_as_ushort(h3)<<16);
            } else {
                *(float2*)(out0 + (size_t)o1*D_ + n) = make_float2(v0, v1);
                *(float2*)(out0 + (size_t)o2*D_ + n) = make_float2(v2, v3);
            }
        }
    }
}

// ---------------- launch ----------------------------------------------------
extern "C" void kernel_launch(void* const* d_in, const int* in_sizes, int n_in,
                              void* d_out, int out_size){
    const float* node  = (const float*)d_in[0];
    const float* Wnw   = (const float*)d_in[1];
    const float* bnw   = (const float*)d_in[2];
    const float* Wself = (const float*)d_in[3];
    const float* bself = (const float*)d_in[4];
    const float* Wedge = (const float*)d_in[5];
    const int*   mask  = (const int*)d_in[6];
    const int*   adj   = (const int*)d_in[7];

    float* out  = (float*)d_out;
    float* outW = out + (size_t)M_*D_;

    cudaFuncSetAttribute(k_gemmA, cudaFuncAttributeMaxDynamicSharedMemorySize, SMEM_A_DYN);
    cudaFuncSetAttribute(k_gemmB, cudaFuncAttributeMaxDynamicSharedMemorySize, SMEM_B_DYN);

    // iteration-invariant preprocessing
    k_bstack<<<(D_*KB_ + 255)/256, 256>>>(Wedge, Wself);
    k_perm  <<<1, 1024>>>(mask);
    k_bits  <<<(E_*B_*N_)/8, 256>>>(adj, mask);
    k_neigh <<<M_/256, 256>>>();
    k_zeroX <<<dim3(10, 128), 256>>>();

    // ---- iteration 0: node -> g_nodeA (+ nhi2) ----
    k_w    <<<M_/8, 256>>>(node, 0, Wnw, bnw, outW, 0);
    k_zt   <<<dim3(16, 8, B_), dim3(32, 32)>>>(node, 0);
    k_gemmA<<<dim3(2, B_*E_*4), 256, SMEM_A_DYN>>>();
    k_gemmB<<<dim3(4, M_/128), 256, SMEM_B_DYN>>>(bself, out, 0, 1);

    // ---- iteration 1: g_nodeA -> d_out ----
    k_w    <<<M_/8, 256>>>(node, 1, Wnw, bnw, outW, 1);
    k_zt   <<<dim3(16, 8, B_), dim3(32, 32)>>>(node, 1);
    k_gemmA<<<dim3(2, B_*E_*4), 256, SMEM_A_DYN>>>();
    k_gemmB<<<dim3(4, M_/128), 256, SMEM_B_DYN>>>(bself, out, 1, 0);
}